// round 12
// baseline (speedup 1.0000x reference)
#include <cuda_runtime.h>
#include <cuda_fp16.h>
#include <cstdint>

// ---------------------------------------------------------------------------
// B=4, N=2048, D=1024. scores sum over (h,d) -> single-head attn over 1024.
// Tensor-core GEMMs via fp16 split:  x = xh + xl (fp16 each)
//   3-term:  A·B ≈ Ah·Bh + Ah·Bl + Al·Bh   (QKV, S gemms)
//   2-term:  A·B ≈ (Ah+Al)·Bh              (O, out gemms)
// 256thr, 2 CTAs/SM, 3-stage cp.async, 1 sync/ktile. Fragment addressing:
// single XORed base per ks + compile-time offsets (folded into LDSM imm).
// ---------------------------------------------------------------------------

#define BM 128
#define BN 128
#define BK 32
#define TILE_B 8192u                    // 128 rows * 64 B (32 fp16, no pad)

// ---------------- scratch (device globals: allocation-guard safe) ----------
__device__ __align__(256) float  g_S[4ull * 2048 * 2048];     // 64 MB
__device__ __align__(256) __half g_xh[8192ull * 1024];
__device__ __align__(256) __half g_xl[8192ull * 1024];
__device__ __align__(256) __half g_wqh[3072ull * 1024];
__device__ __align__(256) __half g_wql[3072ull * 1024];
__device__ __align__(256) __half g_woh[1024ull * 1024];
__device__ __align__(256) __half g_wol[1024ull * 1024];
__device__ __align__(256) __half g_qkvh[8192ull * 3072];
__device__ __align__(256) __half g_qkvl[8192ull * 3072];
__device__ __align__(256) __half g_Sh[4ull * 2048 * 2048];
__device__ __align__(256) __half g_Sl[4ull * 2048 * 2048];
__device__ __align__(256) __half g_Vth[4ull * 1024 * 2048];   // fp16(V)^T
__device__ __align__(256) __half g_Oh[8192ull * 1024];
__device__ __align__(256) __half g_Ol[8192ull * 1024];

// ---------------------------------------------------------------------------
__device__ __forceinline__ uint32_t s2u(const void* p) {
    uint32_t a;
    asm("{ .reg .u64 t; cvta.to.shared.u64 t, %1; cvt.u32.u64 %0, t; }"
        : "=r"(a) : "l"(p));
    return a;
}

__device__ __forceinline__ void cp16(uint32_t dst, const void* src) {
    asm volatile("cp.async.cg.shared.global [%0], [%1], 16;" :: "r"(dst), "l"(src));
}

__device__ __forceinline__ void ldm4(uint32_t* r, uint32_t addr) {
    asm volatile("ldmatrix.sync.aligned.m8n8.x4.shared.b16 {%0,%1,%2,%3}, [%4];"
        : "=r"(r[0]), "=r"(r[1]), "=r"(r[2]), "=r"(r[3]) : "r"(addr));
}

__device__ __forceinline__ void mma_f16(float* c, const uint32_t* a,
                                        uint32_t b0, uint32_t b1) {
    asm volatile(
        "mma.sync.aligned.m16n8k16.row.col.f32.f16.f16.f32 "
        "{%0,%1,%2,%3}, {%4,%5,%6,%7}, {%8,%9}, {%0,%1,%2,%3};"
        : "+f"(c[0]), "+f"(c[1]), "+f"(c[2]), "+f"(c[3])
        : "r"(a[0]), "r"(a[1]), "r"(a[2]), "r"(a[3]), "r"(b0), "r"(b1));
}

__device__ __forceinline__ void split1(float x, __half& h, __half& l) {
    h = __float2half_rn(x);
    l = __float2half_rn(x - __half2float(h));
}

// ---------------------------------------------------------------------------
// fp32 -> (hi, lo) fp16 split, vectorized.
__global__ void __launch_bounds__(256)
split_kernel(const float4* __restrict__ in,
             __half2* __restrict__ h, __half2* __restrict__ l, int n4)
{
    int i = blockIdx.x * blockDim.x + threadIdx.x;
    if (i < n4) {
        float4 v = in[i];
        __half hx, hy, hz, hw, lx, ly, lz, lw;
        split1(v.x, hx, lx); split1(v.y, hy, ly);
        split1(v.z, hz, lz); split1(v.w, hw, lw);
        h[2 * i]     = __halves2half2(hx, hy);
        h[2 * i + 1] = __halves2half2(hz, hw);
        l[2 * i]     = __halves2half2(lx, ly);
        l[2 * i + 1] = __halves2half2(lz, lw);
    }
}

// ---------------------------------------------------------------------------
// Vt[b][d][n] = fp16(V[b][n][d])  (V = qkv cols 2048..3071, reconstructed h+l)
__global__ void __launch_bounds__(256)
transpose_v(const __half* __restrict__ qh, const __half* __restrict__ ql,
            __half* __restrict__ Vth)
{
    __shared__ float t[32][33];
    int b  = blockIdx.z;
    int n0 = blockIdx.x * 32;
    int d0 = blockIdx.y * 32;
    int tx = threadIdx.x, ty = threadIdx.y;   // 32 x 8
    const __half* Vh = qh + (size_t)b * 2048 * 3072 + 2048;
    const __half* Vl = ql + (size_t)b * 2048 * 3072 + 2048;
#pragma unroll
    for (int i = 0; i < 32; i += 8) {
        size_t idx = (size_t)(n0 + ty + i) * 3072 + d0 + tx;
        t[ty + i][tx] = __half2float(Vh[idx]) + __half2float(Vl[idx]);
    }
    __syncthreads();
    __half* dh = Vth + (size_t)b * 1024 * 2048;
#pragma unroll
    for (int i = 0; i < 32; i += 8)
        dh[(size_t)(d0 + ty + i) * 2048 + n0 + tx] = __float2half_rn(t[tx][ty + i]);
}

// ---------------------------------------------------------------------------
// Split NT tensor-core GEMM: C = alpha * A B^T (+bias); A [M,K] (h,l fp16),
// B [N,K] (h[,l]). NT=3: 3-term split; NT=2: (Ah+Al)·Bh.
// Grid (N/BN, M/BM, batch); 256 threads = 8 warps (2m x 4n), 64x32 per warp.
// smem per stage: [Ah][Al][Bh][(Bl)], 128x64B tiles, XOR-swizzled:
//   16B-chunk' = chunk ^ ((row>>1)&3).
// KEY: the XOR term is fragment-index-invariant (i*16>>1 = i*8 == 0 mod 4),
// so all ldmatrix addrs in a ks = (base^kx) + compile-time const -> LDSM imm.
// ---------------------------------------------------------------------------
template <int NT>
__global__ void __launch_bounds__(256, 2)
gemm_nt_split(const __half* __restrict__ Ah, const __half* __restrict__ Al,
              const __half* __restrict__ Bh, const __half* __restrict__ Bl,
              float* __restrict__ Cf,
              __half* __restrict__ Ch, __half* __restrict__ Cl,
              const float* __restrict__ bias,
              int lda, int ldb, int ldc, int K, float alpha,
              long long sA, long long sB, long long sC)
{
    extern __shared__ char smem[];
    constexpr uint32_t STB = (NT == 3 ? 4u : 3u) * TILE_B;   // stage bytes

    const long long offA = (long long)blockIdx.z * sA;
    const long long offB = (long long)blockIdx.z * sB;
    const long long offC = (long long)blockIdx.z * sC;
    Ah += offA; Al += offA;
    Bh += offB; if (NT == 3) Bl += offB;

    const int tid  = threadIdx.x;
    const int wid  = tid >> 5, lane = tid & 31;
    const int wm   = wid & 1,  wn   = wid >> 1;
    const int g    = lane >> 2, t   = lane & 3;
    const int row0 = blockIdx.y * BM;
    const int col0 = blockIdx.x * BN;

    // 128-aligned base (required for the ^32 ks trick)
    const uint32_t smem_u = (s2u(smem) + 127u) & ~127u;

    const __half* Abh = Ah + (size_t)row0 * lda;
    const __half* Abl = Al + (size_t)row0 * lda;
    const __half* Bbh = Bh + (size_t)col0 * ldb;
    const __half* Bbl = (NT == 3) ? (Bl + (size_t)col0 * ldb) : nullptr;

    float acc[4][4][4];
#pragma unroll
    for (int i = 0; i < 4; i++)
#pragma unroll
        for (int j = 0; j < 4; j++)
#pragma unroll
            for (int r = 0; r < 4; r++)
                acc[i][j][r] = 0.0f;

    const int nk = K / BK;

    // loader: thread -> rows (tid>>2, +64), 16B chunk (tid&3), swizzled.
    // row+64 has the same XOR term -> +4096 B constant.
    const int lr = tid >> 2;
    const int lc = tid & 3;
    const uint32_t soff0 = (uint32_t)(lr * 64) +
                           (uint32_t)((lc ^ ((lr >> 1) & 3)) * 16);

    auto load_tile = [&](int kb, int s) {
        const uint32_t st = smem_u + (uint32_t)s * STB + soff0;
        const int kc = kb * BK + lc * 8;
        const __half* a0 = Abh + (size_t)lr * lda + kc;
        const __half* a1 = Abl + (size_t)lr * lda + kc;
        const __half* b0 = Bbh + (size_t)lr * ldb + kc;
        cp16(st,                     a0);
        cp16(st + 4096,              a0 + (size_t)64 * lda);
        cp16(st + TILE_B,            a1);
        cp16(st + TILE_B + 4096,     a1 + (size_t)64 * lda);
        cp16(st + 2 * TILE_B,        b0);
        cp16(st + 2 * TILE_B + 4096, b0 + (size_t)64 * ldb);
        if (NT == 3) {
            const __half* b1 = Bbl + (size_t)lr * ldb + kc;
            cp16(st + 3 * TILE_B,        b1);
            cp16(st + 3 * TILE_B + 4096, b1 + (size_t)64 * ldb);
        }
        asm volatile("cp.async.commit_group;");
    };

    load_tile(0, 0);
    load_tile(1, 1);

    // ---- fragment bases: XOR term is identical for all i/jp
    const int lrow  = lane & 15;
    const int khalf = lane >> 4;
    const uint32_t xorw  = (uint32_t)((khalf ^ ((lrow >> 1) & 3)) * 16);
    const uint32_t aBase = (uint32_t)((wm * 64 + lrow) * 64) + xorw;
    const uint32_t bBase = 2 * TILE_B + (uint32_t)((wn * 32 + lrow) * 64) + xorw;

    int cur = 0;                      // kb % 3
    for (int kb = 0; kb < nk; kb++) {
        if (kb + 1 < nk) asm volatile("cp.async.wait_group 1;");
        else             asm volatile("cp.async.wait_group 0;");
        __syncthreads();

        const uint32_t st = smem_u + (uint32_t)cur * STB;
        const uint32_t aK = st + aBase;
        const uint32_t bK = st + bBase;

#pragma unroll
        for (int ks = 0; ks < 2; ks++) {
            const uint32_t kx = ks ? 32u : 0u;
            const uint32_t aX = aK ^ kx;       // 1 LOP
            const uint32_t bX = bK ^ kx;       // 1 LOP
            uint32_t bh[2][4], bl[2][4], af[4][4];
            // --- B fragments: base + compile-time const (folds into LDSM imm)
            ldm4(bh[0], bX);
            ldm4(bh[1], bX + 1024);
            if (NT == 3) {
                ldm4(bl[0], bX + TILE_B);
                ldm4(bl[1], bX + TILE_B + 1024);
            }
            // --- A-hi fragments
#pragma unroll
            for (int i = 0; i < 4; i++)
                ldm4(af[i], aX + (uint32_t)(i * 1024));
            // --- Ah·Bh
#pragma unroll
            for (int i = 0; i < 4; i++)
#pragma unroll
                for (int j = 0; j < 4; j++) {
                    const int jp = j >> 1, sjj = j & 1;
                    mma_f16(acc[i][j], af[i], bh[jp][sjj], bh[jp][sjj + 2]);
                }
            // --- Ah·Bl
            if (NT == 3) {
#pragma unroll
                for (int i = 0; i < 4; i++)
#pragma unroll
                    for (int j = 0; j < 4; j++) {
                        const int jp = j >> 1, sjj = j & 1;
                        mma_f16(acc[i][j], af[i], bl[jp][sjj], bl[jp][sjj + 2]);
                    }
            }
            // --- A-lo fragments reuse af regs, then Al·Bh
#pragma unroll
            for (int i = 0; i < 4; i++)
                ldm4(af[i], aX + (uint32_t)(TILE_B + i * 1024));
#pragma unroll
            for (int i = 0; i < 4; i++)
#pragma unroll
                for (int j = 0; j < 4; j++) {
                    const int jp = j >> 1, sjj = j & 1;
                    mma_f16(acc[i][j], af[i], bh[jp][sjj], bh[jp][sjj + 2]);
                }
        }

        // prefetch tile kb+2 into the stage consumed at kb-1 (barrier above
        // ordered those reads)
        if (kb + 2 < nk) {
            const int ls = (cur + 2 >= 3) ? cur - 1 : cur + 2;
            load_tile(kb + 2, ls);
        }
        cur = (cur + 1 == 3) ? 0 : cur + 1;
    }

    // ---- epilogue
#pragma unroll
    for (int i = 0; i < 4; i++) {
        const int r = row0 + wm * 64 + i * 16 + g;
#pragma unroll
        for (int j = 0; j < 4; j++) {
            const int c = col0 + wn * 32 + j * 8 + 2 * t;
            float v[4];
            v[0] = alpha * acc[i][j][0];
            v[1] = alpha * acc[i][j][1];
            v[2] = alpha * acc[i][j][2];
            v[3] = alpha * acc[i][j][3];
            if (bias) {
                float bx = bias[c], by = bias[c + 1];
                v[0] += bx; v[1] += by; v[2] += bx; v[3] += by;
            }
            if (Cf) {
                *(float2*)(Cf + offC + (size_t)r * ldc + c)       = make_float2(v[0], v[1]);
                *(float2*)(Cf + offC + (size_t)(r + 8) * ldc + c) = make_float2(v[2], v[3]);
            }
            if (Ch) {
                __half h0, l0, h1, l1, h2, l2, h3, l3;
                split1(v[0], h0, l0); split1(v[1], h1, l1);
                split1(v[2], h2, l2); split1(v[3], h3, l3);
                *(__half2*)(Ch + offC + (size_t)r * ldc + c)       = __halves2half2(h0, h1);
                *(__half2*)(Cl + offC + (size_t)r * ldc + c)       = __halves2half2(l0, l1);
                *(__half2*)(Ch + offC + (size_t)(r + 8) * ldc + c) = __halves2half2(h2, h3);
                *(__half2*)(Cl + offC + (size_t)(r + 8) * ldc + c) = __halves2half2(l2, l3);
            }
        }
    }
}

// ---------------------------------------------------------------------------
// Row softmax over 2048-wide rows (vectorized); writes split fp16 probs.
__global__ void __launch_bounds__(256)
softmax_split(const float4* __restrict__ S4,
              __half2* __restrict__ Sh2, __half2* __restrict__ Sl2)
{
    const size_t b4 = (size_t)blockIdx.x * 512;   // 2048 floats = 512 float4
    const int tid = threadIdx.x;

    float4 va = S4[b4 + tid];
    float4 vb = S4[b4 + tid + 256];

    float m = fmaxf(fmaxf(fmaxf(va.x, va.y), fmaxf(va.z, va.w)),
                    fmaxf(fmaxf(vb.x, vb.y), fmaxf(vb.z, vb.w)));

    __shared__ float red[8];
#pragma unroll
    for (int o = 16; o; o >>= 1) m = fmaxf(m, __shfl_xor_sync(0xffffffffu, m, o));
    if ((tid & 31) == 0) red[tid >> 5] = m;
    __syncthreads();
    m = red[0];
#pragma unroll
    for (int i = 1; i < 8; i++) m = fmaxf(m, red[i]);
    __syncthreads();

    va.x = __expf(va.x - m); va.y = __expf(va.y - m);
    va.z = __expf(va.z - m); va.w = __expf(va.w - m);
    vb.x = __expf(vb.x - m); vb.y = __expf(vb.y - m);
    vb.z = __expf(vb.z - m); vb.w = __expf(vb.w - m);
    float s = va.x + va.y + va.z + va.w + vb.x + vb.y + vb.z + vb.w;

#pragma unroll
    for (int o = 16; o; o >>= 1) s += __shfl_xor_sync(0xffffffffu, s, o);
    if ((tid & 31) == 0) red[tid >> 5] = s;
    __syncthreads();
    s = 0.0f;
#pragma unroll
    for (int i = 0; i < 8; i++) s += red[i];

    const float inv = 1.0f / s;
    const size_t h2base = (size_t)blockIdx.x * 1024;   // 2048 halfs = 1024 half2

    float p[8] = {va.x * inv, va.y * inv, va.z * inv, va.w * inv,
                  vb.x * inv, vb.y * inv, vb.z * inv, vb.w * inv};
    __half hh[8], ll[8];
#pragma unroll
    for (int i = 0; i < 8; i++) split1(p[i], hh[i], ll[i]);

    Sh2[h2base + 2 * tid]             = __halves2half2(hh[0], hh[1]);
    Sh2[h2base + 2 * tid + 1]         = __halves2half2(hh[2], hh[3]);
    Sh2[h2base + 2 * (tid + 256)]     = __halves2half2(hh[4], hh[5]);
    Sh2[h2base + 2 * (tid + 256) + 1] = __halves2half2(hh[6], hh[7]);
    Sl2[h2base + 2 * tid]             = __halves2half2(ll[0], ll[1]);
    Sl2[h2base + 2 * tid + 1]         = __halves2half2(ll[2], ll[3]);
    Sl2[h2base + 2 * (tid + 256)]     = __halves2half2(ll[4], ll[5]);
    Sl2[h2base + 2 * (tid + 256) + 1] = __halves2half2(ll[6], ll[7]);
}

// ---------------------------------------------------------------------------
extern "C" void kernel_launch(void* const* d_in, const int* in_sizes, int n_in,
                              void* d_out, int out_size)
{
    (void)in_sizes; (void)n_in; (void)out_size;
    const float* x     = (const float*)d_in[0];   // [4,2048,1024]
    const float* w_qkv = (const float*)d_in[1];   // [3072,1024]
    const float* w_out = (const float*)d_in[2];   // [1024,1024]
    const float* b_out = (const float*)d_in[3];   // [1024]
    float* out = (float*)d_out;                   // [4,2048,1024]

    float* S;
    __half *xh, *xl, *wqh, *wql, *woh, *wol, *qkvh, *qkvl;
    __half *Sh, *Sl, *Vth, *Oh, *Ol;
    cudaGetSymbolAddress((void**)&S,    g_S);
    cudaGetSymbolAddress((void**)&xh,   g_xh);   cudaGetSymbolAddress((void**)&xl,   g_xl);
    cudaGetSymbolAddress((void**)&wqh,  g_wqh);  cudaGetSymbolAddress((void**)&wql,  g_wql);
    cudaGetSymbolAddress((void**)&woh,  g_woh);  cudaGetSymbolAddress((void**)&wol,  g_wol);
    cudaGetSymbolAddress((void**)&qkvh, g_qkvh); cudaGetSymbolAddress((void**)&qkvl, g_qkvl);
    cudaGetSymbolAddress((void**)&Sh,   g_Sh);   cudaGetSymbolAddress((void**)&Sl,   g_Sl);
    cudaGetSymbolAddress((void**)&Vth,  g_Vth);
    cudaGetSymbolAddress((void**)&Oh,   g_Oh);   cudaGetSymbolAddress((void**)&Ol,   g_Ol);

    const int SM3 = 3 * 4 * TILE_B + 128;   // 98432
    const int SM2 = 3 * 3 * TILE_B + 128;   // 73856
    cudaFuncSetAttribute(gemm_nt_split<3>,
                         cudaFuncAttributeMaxDynamicSharedMemorySize, SM3);
    cudaFuncSetAttribute(gemm_nt_split<2>,
                         cudaFuncAttributeMaxDynamicSharedMemorySize, SM2);

    // 0) split inputs to fp16 (h,l)
    {
        int n4 = 8192 * 1024 / 4;
        split_kernel<<<(n4 + 255) / 256, 256>>>((const float4*)x,
            (__half2*)xh, (__half2*)xl, n4);
        n4 = 3072 * 1024 / 4;
        split_kernel<<<(n4 + 255) / 256, 256>>>((const float4*)w_qkv,
            (__half2*)wqh, (__half2*)wql, n4);
        n4 = 1024 * 1024 / 4;
        split_kernel<<<(n4 + 255) / 256, 256>>>((const float4*)w_out,
            (__half2*)woh, (__half2*)wol, n4);
    }

    // 1) QKV = x @ w_qkv^T : M=8192, N=3072, K=1024 -> split qkv (3-term)
    gemm_nt_split<3><<<dim3(3072 / BN, 8192 / BM, 1), 256, SM3>>>(
        xh, xl, wqh, wql, nullptr, qkvh, qkvl, nullptr,
        1024, 1024, 3072, 1024, 1.0f, 0, 0, 0);

    // 2) Vt[b] = fp16(V[b])^T (only depends on QKV; run before S)
    transpose_v<<<dim3(2048 / 32, 1024 / 32, 4), dim3(32, 8)>>>(qkvh, qkvl, Vth);

    // 3) S[b] = Q[b] @ K[b]^T * 0.125 : fp32 out (3-term)
    gemm_nt_split<3><<<dim3(2048 / BN, 2048 / BM, 4), 256, SM3>>>(
        qkvh, qkvl, qkvh + 1024, qkvl + 1024, S, nullptr, nullptr, nullptr,
        3072, 3072, 2048, 1024, 0.125f,
        2048ll * 3072, 2048ll * 3072, 2048ll * 2048);

    // 4) softmax -> split fp16 probs
    softmax_split<<<4 * 2048, 256>>>((const float4*)S, (__half2*)Sh, (__half2*)Sl);

    // 5) O[b] = P[b] @ V[b] : M=2048, N=1024, K=2048 -> split O (2-term)
    gemm_nt_split<2><<<dim3(1024 / BN, 2048 / BM, 4), 256, SM2>>>(
        Sh, Sl, Vth, nullptr, nullptr, Oh, Ol, nullptr,
        2048, 2048, 1024, 2048, 1.0f,
        2048ll * 2048, 1024ll * 2048, 2048ll * 1024);

    // 6) out = O @ w_out^T + b_out : fp32 out (2-term)
    gemm_nt_split<2><<<dim3(1024 / BN, 8192 / BM, 1), 256, SM2>>>(
        Oh, Ol, woh, nullptr, out, nullptr, nullptr, b_out,
        1024, 1024, 1024, 1024, 1.0f, 0, 0, 0);
}

// round 13
// speedup vs baseline: 1.2987x; 1.2987x over previous
#include <cuda_runtime.h>
#include <cuda_fp16.h>
#include <cstdint>

// ---------------------------------------------------------------------------
// B=4, N=2048, D=1024. scores sum over (h,d) -> single-head attn over 1024.
// ALGEBRAIC FOLD: S = x (Wq^T Wk) x^T,  out = P x (Wv^T Wo^T) + b.
//   W~^T[j,i] = sum_o Wk[o,j] Wq[o,i]      (NT on transposed weight blocks)
//   G~^T[o,i] = sum_j Wo[o,j] Wv[j,i]
//   [y|U] = x @ [W~^T; G~^T]^T  (fused 8192x2048x1024 GEMM)
//   S[b]  = y[b] @ x[b]^T * 0.125 ; P = softmax(S)
//   out   = P @ U + b_out
// GEMMs: fp16 split 3-term (A·B ~ Ah·Bh + Ah·Bl + Al·Bh) except final (2-term).
// GEMM kernel = round-8 best (256thr, 2 CTAs/SM, 3-stage cp.async, XOR swizzle).
// ---------------------------------------------------------------------------

#define BM 128
#define BN 128
#define BK 32
#define TILE_B 8192u                    // 128 rows * 64 B (32 fp16, no pad)

// ---------------- scratch (device globals: allocation-guard safe) ----------
__device__ __align__(256) float  g_S[4ull * 2048 * 2048];     // 64 MB
__device__ __align__(256) __half g_xh[8192ull * 1024];
__device__ __align__(256) __half g_xl[8192ull * 1024];
__device__ __align__(256) float  g_bufA[2048ull * 1024];      // [Wk^T ; Wo]
__device__ __align__(256) float  g_bufB[2048ull * 1024];      // [Wq^T ; Wv^T]
__device__ __align__(256) __half g_bAh[2048ull * 1024];
__device__ __align__(256) __half g_bAl[2048ull * 1024];
__device__ __align__(256) __half g_bBh[2048ull * 1024];
__device__ __align__(256) __half g_bBl[2048ull * 1024];
__device__ __align__(256) __half g_Wch[2048ull * 1024];       // [W~^T ; G~^T] hi
__device__ __align__(256) __half g_Wcl[2048ull * 1024];       // lo
__device__ __align__(256) __half g_yUh[8192ull * 2048];       // [y | U] hi
__device__ __align__(256) __half g_yUl[8192ull * 2048];       // lo
__device__ __align__(256) __half g_Sh[4ull * 2048 * 2048];
__device__ __align__(256) __half g_Sl[4ull * 2048 * 2048];
__device__ __align__(256) __half g_Ut[4ull * 1024 * 2048];    // U^T per batch

// ---------------------------------------------------------------------------
__device__ __forceinline__ uint32_t s2u(const void* p) {
    uint32_t a;
    asm("{ .reg .u64 t; cvta.to.shared.u64 t, %1; cvt.u32.u64 %0, t; }"
        : "=r"(a) : "l"(p));
    return a;
}

__device__ __forceinline__ void cp16(uint32_t dst, const void* src) {
    asm volatile("cp.async.cg.shared.global [%0], [%1], 16;" :: "r"(dst), "l"(src));
}

__device__ __forceinline__ void ldm4(uint32_t* r, uint32_t addr) {
    asm volatile("ldmatrix.sync.aligned.m8n8.x4.shared.b16 {%0,%1,%2,%3}, [%4];"
        : "=r"(r[0]), "=r"(r[1]), "=r"(r[2]), "=r"(r[3]) : "r"(addr));
}

__device__ __forceinline__ void mma_f16(float* c, const uint32_t* a,
                                        uint32_t b0, uint32_t b1) {
    asm volatile(
        "mma.sync.aligned.m16n8k16.row.col.f32.f16.f16.f32 "
        "{%0,%1,%2,%3}, {%4,%5,%6,%7}, {%8,%9}, {%0,%1,%2,%3};"
        : "+f"(c[0]), "+f"(c[1]), "+f"(c[2]), "+f"(c[3])
        : "r"(a[0]), "r"(a[1]), "r"(a[2]), "r"(a[3]), "r"(b0), "r"(b1));
}

__device__ __forceinline__ void split1(float x, __half& h, __half& l) {
    h = __float2half_rn(x);
    l = __float2half_rn(x - __half2float(h));
}

// ---------------------------------------------------------------------------
// fp32 -> (hi, lo) fp16 split, vectorized.
__global__ void __launch_bounds__(256)
split_kernel(const float4* __restrict__ in,
             __half2* __restrict__ h, __half2* __restrict__ l, int n4)
{
    int i = blockIdx.x * blockDim.x + threadIdx.x;
    if (i < n4) {
        float4 v = in[i];
        __half hx, hy, hz, hw, lx, ly, lz, lw;
        split1(v.x, hx, lx); split1(v.y, hy, ly);
        split1(v.z, hz, lz); split1(v.w, hw, lw);
        h[2 * i]     = __halves2half2(hx, hy);
        h[2 * i + 1] = __halves2half2(hz, hw);
        l[2 * i]     = __halves2half2(lx, ly);
        l[2 * i + 1] = __halves2half2(lz, lw);
    }
}

// ---------------------------------------------------------------------------
// fp32 1024x1024 transpose: dst[c][r] = src[r][c]
__global__ void __launch_bounds__(256)
transpose32f(const float* __restrict__ src, float* __restrict__ dst)
{
    __shared__ float t[32][33];
    int r0 = blockIdx.x * 32, c0 = blockIdx.y * 32;
    int tx = threadIdx.x, ty = threadIdx.y;   // 32 x 8
#pragma unroll
    for (int i = 0; i < 32; i += 8)
        t[ty + i][tx] = src[(size_t)(r0 + ty + i) * 1024 + c0 + tx];
    __syncthreads();
#pragma unroll
    for (int i = 0; i < 32; i += 8)
        dst[(size_t)(c0 + ty + i) * 1024 + r0 + tx] = t[tx][ty + i];
}

// ---------------------------------------------------------------------------
// Ut[b][o][m] = yU[b*2048 + m][1024 + o]  (fp16, U = right half of yU)
__global__ void __launch_bounds__(256)
transpose_u(const __half* __restrict__ yU, __half* __restrict__ Ut)
{
    __shared__ __half t[32][34];
    int b  = blockIdx.z;
    int m0 = blockIdx.x * 32;
    int o0 = blockIdx.y * 32;
    int tx = threadIdx.x, ty = threadIdx.y;   // 32 x 8
    const __half* s = yU + (size_t)b * 2048 * 2048 + 1024;
#pragma unroll
    for (int i = 0; i < 32; i += 8)
        t[ty + i][tx] = s[(size_t)(m0 + ty + i) * 2048 + o0 + tx];
    __syncthreads();
    __half* d = Ut + (size_t)b * 1024 * 2048;
#pragma unroll
    for (int i = 0; i < 32; i += 8)
        d[(size_t)(o0 + ty + i) * 2048 + m0 + tx] = t[tx][ty + i];
}

// ---------------------------------------------------------------------------
// Split NT tensor-core GEMM (round-8 best): C = alpha*A B^T (+bias);
// A [M,K] (h,l fp16), B [N,K] (h[,l]). NT=3: 3-term; NT=2: (Ah+Al)·Bh.
// Grid (N/BN, M/BM, batch); 256 threads = 8 warps (2m x 4n), 64x32 per warp.
// ---------------------------------------------------------------------------
template <int NT>
__global__ void __launch_bounds__(256, 2)
gemm_nt_split(const __half* __restrict__ Ah, const __half* __restrict__ Al,
              const __half* __restrict__ Bh, const __half* __restrict__ Bl,
              float* __restrict__ Cf,
              __half* __restrict__ Ch, __half* __restrict__ Cl,
              const float* __restrict__ bias,
              int lda, int ldb, int ldc, int K, float alpha,
              long long sA, long long sB, long long sC)
{
    extern __shared__ char smem[];
    constexpr uint32_t STB = (NT == 3 ? 4u : 3u) * TILE_B;

    const long long offA = (long long)blockIdx.z * sA;
    const long long offB = (long long)blockIdx.z * sB;
    const long long offC = (long long)blockIdx.z * sC;
    Ah += offA; Al += offA;
    Bh += offB; if (NT == 3) Bl += offB;

    const int tid  = threadIdx.x;
    const int wid  = tid >> 5, lane = tid & 31;
    const int wm   = wid & 1,  wn   = wid >> 1;
    const int g    = lane >> 2, t   = lane & 3;
    const int row0 = blockIdx.y * BM;
    const int col0 = blockIdx.x * BN;

    const uint32_t smem_u = s2u(smem);

    const __half* Abh = Ah + (size_t)row0 * lda;
    const __half* Abl = Al + (size_t)row0 * lda;
    const __half* Bbh = Bh + (size_t)col0 * ldb;
    const __half* Bbl = (NT == 3) ? (Bl + (size_t)col0 * ldb) : nullptr;

    float acc[4][4][4];
#pragma unroll
    for (int i = 0; i < 4; i++)
#pragma unroll
        for (int j = 0; j < 4; j++)
#pragma unroll
            for (int r = 0; r < 4; r++)
                acc[i][j][r] = 0.0f;

    const int nk = K / BK;

    const int lr = tid >> 2;
    const int lc = tid & 3;

    auto load_tile = [&](int kb, int s) {
        const uint32_t st = smem_u + (uint32_t)s * STB;
        const int kc = kb * BK + lc * 8;
#pragma unroll
        for (int hh = 0; hh < 2; hh++) {
            const int r = lr + hh * 64;
            const uint32_t phys = (uint32_t)(lc ^ ((r >> 1) & 3));
            const uint32_t off  = (uint32_t)(r * 64) + phys * 16u;
            cp16(st + off,              Abh + (size_t)r * lda + kc);
            cp16(st + TILE_B + off,     Abl + (size_t)r * lda + kc);
            cp16(st + 2 * TILE_B + off, Bbh + (size_t)r * ldb + kc);
            if (NT == 3)
                cp16(st + 3 * TILE_B + off, Bbl + (size_t)r * ldb + kc);
        }
    };

    load_tile(0, 0);
    asm volatile("cp.async.commit_group;");
    load_tile(1, 1);
    asm volatile("cp.async.commit_group;");

    const int lrow  = lane & 15;
    const int khalf = lane >> 4;

    int cur = 0;
    for (int kb = 0; kb < nk; kb++) {
        if (kb + 1 < nk) asm volatile("cp.async.wait_group 1;");
        else             asm volatile("cp.async.wait_group 0;");
        __syncthreads();

        const uint32_t st = smem_u + (uint32_t)cur * STB;

#pragma unroll
        for (int ks = 0; ks < 2; ks++) {
            uint32_t bh[2][4], bl[2][4], af[4][4];
#pragma unroll
            for (int jp = 0; jp < 2; jp++) {
                const int row = wn * 32 + jp * 16 + lrow;
                const uint32_t phys = (uint32_t)((ks * 2 + khalf) ^ ((row >> 1) & 3));
                const uint32_t bd = st + 2 * TILE_B + (uint32_t)(row * 64) + phys * 16u;
                ldm4(bh[jp], bd);
                if (NT == 3) ldm4(bl[jp], bd + TILE_B);
            }
#pragma unroll
            for (int i = 0; i < 4; i++) {
                const int row = wm * 64 + i * 16 + lrow;
                const uint32_t phys = (uint32_t)((ks * 2 + khalf) ^ ((row >> 1) & 3));
                ldm4(af[i], st + (uint32_t)(row * 64) + phys * 16u);
            }
#pragma unroll
            for (int i = 0; i < 4; i++)
#pragma unroll
                for (int j = 0; j < 4; j++) {
                    const int jp = j >> 1, sjj = j & 1;
                    mma_f16(acc[i][j], af[i], bh[jp][sjj], bh[jp][sjj + 2]);
                }
            if (NT == 3) {
#pragma unroll
                for (int i = 0; i < 4; i++)
#pragma unroll
                    for (int j = 0; j < 4; j++) {
                        const int jp = j >> 1, sjj = j & 1;
                        mma_f16(acc[i][j], af[i], bl[jp][sjj], bl[jp][sjj + 2]);
                    }
            }
#pragma unroll
            for (int i = 0; i < 4; i++) {
                const int row = wm * 64 + i * 16 + lrow;
                const uint32_t phys = (uint32_t)((ks * 2 + khalf) ^ ((row >> 1) & 3));
                ldm4(af[i], st + TILE_B + (uint32_t)(row * 64) + phys * 16u);
            }
#pragma unroll
            for (int i = 0; i < 4; i++)
#pragma unroll
                for (int j = 0; j < 4; j++) {
                    const int jp = j >> 1, sjj = j & 1;
                    mma_f16(acc[i][j], af[i], bh[jp][sjj], bh[jp][sjj + 2]);
                }
        }

        if (kb + 2 < nk) {
            const int ls = (cur + 2 >= 3) ? cur - 1 : cur + 2;
            load_tile(kb + 2, ls);
            asm volatile("cp.async.commit_group;");
        }
        cur = (cur + 1 == 3) ? 0 : cur + 1;
    }

    // ---- epilogue
#pragma unroll
    for (int i = 0; i < 4; i++) {
        const int r = row0 + wm * 64 + i * 16 + g;
#pragma unroll
        for (int j = 0; j < 4; j++) {
            const int c = col0 + wn * 32 + j * 8 + 2 * t;
            float v[4];
            v[0] = alpha * acc[i][j][0];
            v[1] = alpha * acc[i][j][1];
            v[2] = alpha * acc[i][j][2];
            v[3] = alpha * acc[i][j][3];
            if (bias) {
                float bx = bias[c], by = bias[c + 1];
                v[0] += bx; v[1] += by; v[2] += bx; v[3] += by;
            }
            if (Cf) {
                *(float2*)(Cf + offC + (size_t)r * ldc + c)       = make_float2(v[0], v[1]);
                *(float2*)(Cf + offC + (size_t)(r + 8) * ldc + c) = make_float2(v[2], v[3]);
            }
            if (Ch) {
                __half h0, l0, h1, l1, h2, l2, h3, l3;
                split1(v[0], h0, l0); split1(v[1], h1, l1);
                split1(v[2], h2, l2); split1(v[3], h3, l3);
                *(__half2*)(Ch + offC + (size_t)r * ldc + c)       = __halves2half2(h0, h1);
                *(__half2*)(Cl + offC + (size_t)r * ldc + c)       = __halves2half2(l0, l1);
                *(__half2*)(Ch + offC + (size_t)(r + 8) * ldc + c) = __halves2half2(h2, h3);
                *(__half2*)(Cl + offC + (size_t)(r + 8) * ldc + c) = __halves2half2(l2, l3);
            }
        }
    }
}

// ---------------------------------------------------------------------------
// Row softmax over 2048-wide rows (vectorized); writes split fp16 probs.
__global__ void __launch_bounds__(256)
softmax_split(const float4* __restrict__ S4,
              __half2* __restrict__ Sh2, __half2* __restrict__ Sl2)
{
    const size_t b4 = (size_t)blockIdx.x * 512;
    const int tid = threadIdx.x;

    float4 va = S4[b4 + tid];
    float4 vb = S4[b4 + tid + 256];

    float m = fmaxf(fmaxf(fmaxf(va.x, va.y), fmaxf(va.z, va.w)),
                    fmaxf(fmaxf(vb.x, vb.y), fmaxf(vb.z, vb.w)));

    __shared__ float red[8];
#pragma unroll
    for (int o = 16; o; o >>= 1) m = fmaxf(m, __shfl_xor_sync(0xffffffffu, m, o));
    if ((tid & 31) == 0) red[tid >> 5] = m;
    __syncthreads();
    m = red[0];
#pragma unroll
    for (int i = 1; i < 8; i++) m = fmaxf(m, red[i]);
    __syncthreads();

    va.x = __expf(va.x - m); va.y = __expf(va.y - m);
    va.z = __expf(va.z - m); va.w = __expf(va.w - m);
    vb.x = __expf(vb.x - m); vb.y = __expf(vb.y - m);
    vb.z = __expf(vb.z - m); vb.w = __expf(vb.w - m);
    float s = va.x + va.y + va.z + va.w + vb.x + vb.y + vb.z + vb.w;

#pragma unroll
    for (int o = 16; o; o >>= 1) s += __shfl_xor_sync(0xffffffffu, s, o);
    if ((tid & 31) == 0) red[tid >> 5] = s;
    __syncthreads();
    s = 0.0f;
#pragma unroll
    for (int i = 0; i < 8; i++) s += red[i];

    const float inv = 1.0f / s;
    const size_t h2base = (size_t)blockIdx.x * 1024;

    float p[8] = {va.x * inv, va.y * inv, va.z * inv, va.w * inv,
                  vb.x * inv, vb.y * inv, vb.z * inv, vb.w * inv};
    __half hh[8], ll[8];
#pragma unroll
    for (int i = 0; i < 8; i++) split1(p[i], hh[i], ll[i]);

    Sh2[h2base + 2 * tid]             = __halves2half2(hh[0], hh[1]);
    Sh2[h2base + 2 * tid + 1]         = __halves2half2(hh[2], hh[3]);
    Sh2[h2base + 2 * (tid + 256)]     = __halves2half2(hh[4], hh[5]);
    Sh2[h2base + 2 * (tid + 256) + 1] = __halves2half2(hh[6], hh[7]);
    Sl2[h2base + 2 * tid]             = __halves2half2(ll[0], ll[1]);
    Sl2[h2base + 2 * tid + 1]         = __halves2half2(ll[2], ll[3]);
    Sl2[h2base + 2 * (tid + 256)]     = __halves2half2(ll[4], ll[5]);
    Sl2[h2base + 2 * (tid + 256) + 1] = __halves2half2(ll[6], ll[7]);
}

// ---------------------------------------------------------------------------
extern "C" void kernel_launch(void* const* d_in, const int* in_sizes, int n_in,
                              void* d_out, int out_size)
{
    (void)in_sizes; (void)n_in; (void)out_size;
    const float* x     = (const float*)d_in[0];   // [4,2048,1024]
    const float* w_qkv = (const float*)d_in[1];   // [3072,1024]
    const float* w_out = (const float*)d_in[2];   // [1024,1024]
    const float* b_out = (const float*)d_in[3];   // [1024]
    float* out = (float*)d_out;                   // [4,2048,1024]

    float *S, *bufA, *bufB;
    __half *xh, *xl, *bAh, *bAl, *bBh, *bBl, *Wch, *Wcl, *yUh, *yUl, *Sh, *Sl, *Ut;
    cudaGetSymbolAddress((void**)&S,    g_S);
    cudaGetSymbolAddress((void**)&xh,   g_xh);   cudaGetSymbolAddress((void**)&xl,   g_xl);
    cudaGetSymbolAddress((void**)&bufA, g_bufA); cudaGetSymbolAddress((void**)&bufB, g_bufB);
    cudaGetSymbolAddress((void**)&bAh,  g_bAh);  cudaGetSymbolAddress((void**)&bAl,  g_bAl);
    cudaGetSymbolAddress((void**)&bBh,  g_bBh);  cudaGetSymbolAddress((void**)&bBl,  g_bBl);
    cudaGetSymbolAddress((void**)&Wch,  g_Wch);  cudaGetSymbolAddress((void**)&Wcl,  g_Wcl);
    cudaGetSymbolAddress((void**)&yUh,  g_yUh);  cudaGetSymbolAddress((void**)&yUl,  g_yUl);
    cudaGetSymbolAddress((void**)&Sh,   g_Sh);   cudaGetSymbolAddress((void**)&Sl,   g_Sl);
    cudaGetSymbolAddress((void**)&Ut,   g_Ut);

    const int SM3 = 3 * 4 * TILE_B;   // 98304
    const int SM2 = 3 * 3 * TILE_B;   // 73728
    cudaFuncSetAttribute(gemm_nt_split<3>,
                         cudaFuncAttributeMaxDynamicSharedMemorySize, SM3);
    cudaFuncSetAttribute(gemm_nt_split<2>,
                         cudaFuncAttributeMaxDynamicSharedMemorySize, SM2);

    // 0) split x; build packed weight operands
    {
        int n4 = 8192 * 1024 / 4;
        split_kernel<<<(n4 + 255) / 256, 256>>>((const float4*)x,
            (__half2*)xh, (__half2*)xl, n4);
    }
    // bufA = [Wk^T ; Wo],  bufB = [Wq^T ; Wv^T]
    transpose32f<<<dim3(32, 32), dim3(32, 8)>>>(w_qkv + 1024ll * 1024, bufA);
    transpose32f<<<dim3(32, 32), dim3(32, 8)>>>(w_qkv,                 bufB);
    transpose32f<<<dim3(32, 32), dim3(32, 8)>>>(w_qkv + 2048ll * 1024, bufB + 1024ll * 1024);
    cudaMemcpyAsync(bufA + 1024ll * 1024, w_out, 1024ll * 1024 * 4,
                    cudaMemcpyDeviceToDevice);
    {
        int n4 = 2048 * 1024 / 4;
        split_kernel<<<(n4 + 255) / 256, 256>>>((const float4*)bufA,
            (__half2*)bAh, (__half2*)bAl, n4);
        split_kernel<<<(n4 + 255) / 256, 256>>>((const float4*)bufB,
            (__half2*)bBh, (__half2*)bBl, n4);
    }

    // 1) weight products (batched z=2): Wc[0]=W~^T (Wk^T·Wq^T-NT), Wc[1]=G~^T
    gemm_nt_split<3><<<dim3(8, 8, 2), 256, SM3>>>(
        bAh, bAl, bBh, bBl, nullptr, Wch, Wcl, nullptr,
        1024, 1024, 1024, 1024, 1.0f,
        1024ll * 1024, 1024ll * 1024, 1024ll * 1024);

    // 2) [y|U] = x @ Wc^T : M=8192, N=2048, K=1024 -> split yU
    gemm_nt_split<3><<<dim3(16, 64, 1), 256, SM3>>>(
        xh, xl, Wch, Wcl, nullptr, yUh, yUl, nullptr,
        1024, 1024, 2048, 1024, 1.0f, 0, 0, 0);

    // 3) S[b] = y[b] @ x[b]^T * 0.125 : fp32 out
    gemm_nt_split<3><<<dim3(16, 16, 4), 256, SM3>>>(
        yUh, yUl, xh, xl, S, nullptr, nullptr, nullptr,
        2048, 1024, 2048, 1024, 0.125f,
        2048ll * 2048, 2048ll * 1024, 2048ll * 2048);

    // 4) softmax -> split fp16 probs
    softmax_split<<<4 * 2048, 256>>>((const float4*)S, (__half2*)Sh, (__half2*)Sl);

    // 5) Ut[b] = U[b]^T (U = right half of yU, hi part)
    transpose_u<<<dim3(64, 32, 4), dim3(32, 8)>>>(yUh, Ut);

    // 6) out = P @ U + b_out : M=2048, N=1024, K=2048 (2-term)
    gemm_nt_split<2><<<dim3(8, 16, 4), 256, SM2>>>(
        Sh, Sl, Ut, nullptr, out, nullptr, nullptr, b_out,
        2048, 2048, 1024, 2048, 1.0f,
        2048ll * 2048, 1024ll * 2048, 2048ll * 1024);
}

// round 14
// speedup vs baseline: 1.4646x; 1.1277x over previous
#include <cuda_runtime.h>
#include <cuda_fp16.h>
#include <cstdint>

// ---------------------------------------------------------------------------
// B=4, N=2048, D=1024. scores sum over (h,d) -> single-head attn over 1024.
// ALGEBRAIC FOLD: S = x (Wq^T Wk) x^T,  out = P x (Wv^T Wo^T) + b.
//   [y|U] = x @ [W~^T; G~^T]^T  (fused 8192x2048x1024 GEMM)
//   S[b]  = y[b] @ x[b]^T * 0.125 ; P = softmax(S)
//   out   = Ph @ U^T_h + b_out          (1-term: P,U precision-insensitive)
// GEMMs: fp16 split. NT=3 (3-term) for weight-products / yU / S;
// NT=1 (hi-only) for the final P@U.
// ---------------------------------------------------------------------------

#define BM 128
#define BN 128
#define BK 32
#define TILE_B 8192u                    // 128 rows * 64 B (32 fp16, no pad)

// ---------------- scratch (device globals: allocation-guard safe) ----------
__device__ __align__(256) float  g_S[4ull * 2048 * 2048];     // 64 MB
__device__ __align__(256) __half g_xh[8192ull * 1024];
__device__ __align__(256) __half g_xl[8192ull * 1024];
__device__ __align__(256) float  g_bufA[2048ull * 1024];      // [Wk^T ; Wo]
__device__ __align__(256) float  g_bufB[2048ull * 1024];      // [Wq^T ; Wv^T]
__device__ __align__(256) __half g_bAh[2048ull * 1024];
__device__ __align__(256) __half g_bAl[2048ull * 1024];
__device__ __align__(256) __half g_bBh[2048ull * 1024];
__device__ __align__(256) __half g_bBl[2048ull * 1024];
__device__ __align__(256) __half g_Wch[2048ull * 1024];       // [W~^T ; G~^T] hi
__device__ __align__(256) __half g_Wcl[2048ull * 1024];       // lo
__device__ __align__(256) __half g_yUh[8192ull * 2048];       // [y | U] hi
__device__ __align__(256) __half g_yUl[8192ull * 2048];       // lo
__device__ __align__(256) __half g_Sh[4ull * 2048 * 2048];    // P hi
__device__ __align__(256) __half g_Ut[4ull * 1024 * 2048];    // U^T per batch

// ---------------------------------------------------------------------------
__device__ __forceinline__ uint32_t s2u(const void* p) {
    uint32_t a;
    asm("{ .reg .u64 t; cvta.to.shared.u64 t, %1; cvt.u32.u64 %0, t; }"
        : "=r"(a) : "l"(p));
    return a;
}

__device__ __forceinline__ void cp16(uint32_t dst, const void* src) {
    asm volatile("cp.async.cg.shared.global [%0], [%1], 16;" :: "r"(dst), "l"(src));
}

__device__ __forceinline__ void ldm4(uint32_t* r, uint32_t addr) {
    asm volatile("ldmatrix.sync.aligned.m8n8.x4.shared.b16 {%0,%1,%2,%3}, [%4];"
        : "=r"(r[0]), "=r"(r[1]), "=r"(r[2]), "=r"(r[3]) : "r"(addr));
}

__device__ __forceinline__ void mma_f16(float* c, const uint32_t* a,
                                        uint32_t b0, uint32_t b1) {
    asm volatile(
        "mma.sync.aligned.m16n8k16.row.col.f32.f16.f16.f32 "
        "{%0,%1,%2,%3}, {%4,%5,%6,%7}, {%8,%9}, {%0,%1,%2,%3};"
        : "+f"(c[0]), "+f"(c[1]), "+f"(c[2]), "+f"(c[3])
        : "r"(a[0]), "r"(a[1]), "r"(a[2]), "r"(a[3]), "r"(b0), "r"(b1));
}

__device__ __forceinline__ void split1(float x, __half& h, __half& l) {
    h = __float2half_rn(x);
    l = __float2half_rn(x - __half2float(h));
}

// ---------------------------------------------------------------------------
// fp32 -> (hi, lo) fp16 split, vectorized.
__global__ void __launch_bounds__(256)
split_kernel(const float4* __restrict__ in,
             __half2* __restrict__ h, __half2* __restrict__ l, int n4)
{
    int i = blockIdx.x * blockDim.x + threadIdx.x;
    if (i < n4) {
        float4 v = in[i];
        __half hx, hy, hz, hw, lx, ly, lz, lw;
        split1(v.x, hx, lx); split1(v.y, hy, ly);
        split1(v.z, hz, lz); split1(v.w, hw, lw);
        h[2 * i]     = __halves2half2(hx, hy);
        h[2 * i + 1] = __halves2half2(hz, hw);
        l[2 * i]     = __halves2half2(lx, ly);
        l[2 * i + 1] = __halves2half2(lz, lw);
    }
}

// ---------------------------------------------------------------------------
// fp32 1024x1024 transpose: dst[c][r] = src[r][c]
__global__ void __launch_bounds__(256)
transpose32f(const float* __restrict__ src, float* __restrict__ dst)
{
    __shared__ float t[32][33];
    int r0 = blockIdx.x * 32, c0 = blockIdx.y * 32;
    int tx = threadIdx.x, ty = threadIdx.y;   // 32 x 8
#pragma unroll
    for (int i = 0; i < 32; i += 8)
        t[ty + i][tx] = src[(size_t)(r0 + ty + i) * 1024 + c0 + tx];
    __syncthreads();
#pragma unroll
    for (int i = 0; i < 32; i += 8)
        dst[(size_t)(c0 + ty + i) * 1024 + r0 + tx] = t[tx][ty + i];
}

// ---------------------------------------------------------------------------
// Ut[b][o][m] = yU[b*2048 + m][1024 + o]  (fp16, U = right half of yU)
__global__ void __launch_bounds__(256)
transpose_u(const __half* __restrict__ yU, __half* __restrict__ Ut)
{
    __shared__ __half t[32][34];
    int b  = blockIdx.z;
    int m0 = blockIdx.x * 32;
    int o0 = blockIdx.y * 32;
    int tx = threadIdx.x, ty = threadIdx.y;   // 32 x 8
    const __half* s = yU + (size_t)b * 2048 * 2048 + 1024;
#pragma unroll
    for (int i = 0; i < 32; i += 8)
        t[ty + i][tx] = s[(size_t)(m0 + ty + i) * 2048 + o0 + tx];
    __syncthreads();
    __half* d = Ut + (size_t)b * 1024 * 2048;
#pragma unroll
    for (int i = 0; i < 32; i += 8)
        d[(size_t)(o0 + ty + i) * 2048 + m0 + tx] = t[tx][ty + i];
}

// ---------------------------------------------------------------------------
// Split NT tensor-core GEMM: C = alpha*A B^T (+bias);
// NT=3: Ah·Bh + Ah·Bl + Al·Bh;  NT=2: (Ah+Al)·Bh;  NT=1: Ah·Bh.
// Grid (N/BN, M/BM, batch); 256 threads = 8 warps (2m x 4n), 64x32 per warp.
// smem per stage: [Ah][Al?][Bh][Bl?], 128x64B tiles, XOR-swizzled.
// ---------------------------------------------------------------------------
template <int NT>
__global__ void __launch_bounds__(256, 2)
gemm_nt_split(const __half* __restrict__ Ah, const __half* __restrict__ Al,
              const __half* __restrict__ Bh, const __half* __restrict__ Bl,
              float* __restrict__ Cf,
              __half* __restrict__ Ch, __half* __restrict__ Cl,
              const float* __restrict__ bias,
              int lda, int ldb, int ldc, int K, float alpha,
              long long sA, long long sB, long long sC)
{
    extern __shared__ char smem[];
    constexpr uint32_t NTILES = (NT == 3) ? 4u : (NT == 2 ? 3u : 2u);
    constexpr uint32_t STB   = NTILES * TILE_B;
    constexpr uint32_t O_BH  = (NT >= 2) ? 2u * TILE_B : TILE_B;

    const long long offA = (long long)blockIdx.z * sA;
    const long long offB = (long long)blockIdx.z * sB;
    const long long offC = (long long)blockIdx.z * sC;
    Ah += offA; if (NT >= 2) Al += offA;
    Bh += offB; if (NT == 3) Bl += offB;

    const int tid  = threadIdx.x;
    const int wid  = tid >> 5, lane = tid & 31;
    const int wm   = wid & 1,  wn   = wid >> 1;
    const int g    = lane >> 2, t   = lane & 3;
    const int row0 = blockIdx.y * BM;
    const int col0 = blockIdx.x * BN;

    const uint32_t smem_u = s2u(smem);

    const __half* Abh = Ah + (size_t)row0 * lda;
    const __half* Abl = (NT >= 2) ? (Al + (size_t)row0 * lda) : nullptr;
    const __half* Bbh = Bh + (size_t)col0 * ldb;
    const __half* Bbl = (NT == 3) ? (Bl + (size_t)col0 * ldb) : nullptr;

    float acc[4][4][4];
#pragma unroll
    for (int i = 0; i < 4; i++)
#pragma unroll
        for (int j = 0; j < 4; j++)
#pragma unroll
            for (int r = 0; r < 4; r++)
                acc[i][j][r] = 0.0f;

    const int nk = K / BK;

    const int lr = tid >> 2;
    const int lc = tid & 3;

    auto load_tile = [&](int kb, int s) {
        const uint32_t st = smem_u + (uint32_t)s * STB;
        const int kc = kb * BK + lc * 8;
#pragma unroll
        for (int hh = 0; hh < 2; hh++) {
            const int r = lr + hh * 64;
            const uint32_t phys = (uint32_t)(lc ^ ((r >> 1) & 3));
            const uint32_t off  = (uint32_t)(r * 64) + phys * 16u;
            cp16(st + off, Abh + (size_t)r * lda + kc);
            if (NT >= 2)
                cp16(st + TILE_B + off, Abl + (size_t)r * lda + kc);
            cp16(st + O_BH + off, Bbh + (size_t)r * ldb + kc);
            if (NT == 3)
                cp16(st + 3 * TILE_B + off, Bbl + (size_t)r * ldb + kc);
        }
    };

    load_tile(0, 0);
    asm volatile("cp.async.commit_group;");
    load_tile(1, 1);
    asm volatile("cp.async.commit_group;");

    const int lrow  = lane & 15;
    const int khalf = lane >> 4;

    int cur = 0;
    for (int kb = 0; kb < nk; kb++) {
        if (kb + 1 < nk) asm volatile("cp.async.wait_group 1;");
        else             asm volatile("cp.async.wait_group 0;");
        __syncthreads();

        const uint32_t st = smem_u + (uint32_t)cur * STB;

#pragma unroll
        for (int ks = 0; ks < 2; ks++) {
            uint32_t bh[2][4], bl[2][4], af[4][4];
#pragma unroll
            for (int jp = 0; jp < 2; jp++) {
                const int row = wn * 32 + jp * 16 + lrow;
                const uint32_t phys = (uint32_t)((ks * 2 + khalf) ^ ((row >> 1) & 3));
                const uint32_t bd = st + O_BH + (uint32_t)(row * 64) + phys * 16u;
                ldm4(bh[jp], bd);
                if (NT == 3) ldm4(bl[jp], bd + TILE_B);
            }
#pragma unroll
            for (int i = 0; i < 4; i++) {
                const int row = wm * 64 + i * 16 + lrow;
                const uint32_t phys = (uint32_t)((ks * 2 + khalf) ^ ((row >> 1) & 3));
                ldm4(af[i], st + (uint32_t)(row * 64) + phys * 16u);
            }
#pragma unroll
            for (int i = 0; i < 4; i++)
#pragma unroll
                for (int j = 0; j < 4; j++) {
                    const int jp = j >> 1, sjj = j & 1;
                    mma_f16(acc[i][j], af[i], bh[jp][sjj], bh[jp][sjj + 2]);
                }
            if (NT == 3) {
#pragma unroll
                for (int i = 0; i < 4; i++)
#pragma unroll
                    for (int j = 0; j < 4; j++) {
                        const int jp = j >> 1, sjj = j & 1;
                        mma_f16(acc[i][j], af[i], bl[jp][sjj], bl[jp][sjj + 2]);
                    }
            }
            if (NT >= 2) {
#pragma unroll
                for (int i = 0; i < 4; i++) {
                    const int row = wm * 64 + i * 16 + lrow;
                    const uint32_t phys = (uint32_t)((ks * 2 + khalf) ^ ((row >> 1) & 3));
                    ldm4(af[i], st + TILE_B + (uint32_t)(row * 64) + phys * 16u);
                }
#pragma unroll
                for (int i = 0; i < 4; i++)
#pragma unroll
                    for (int j = 0; j < 4; j++) {
                        const int jp = j >> 1, sjj = j & 1;
                        mma_f16(acc[i][j], af[i], bh[jp][sjj], bh[jp][sjj + 2]);
                    }
            }
        }

        if (kb + 2 < nk) {
            const int ls = (cur + 2 >= 3) ? cur - 1 : cur + 2;
            load_tile(kb + 2, ls);
            asm volatile("cp.async.commit_group;");
        }
        cur = (cur + 1 == 3) ? 0 : cur + 1;
    }

    // ---- epilogue
#pragma unroll
    for (int i = 0; i < 4; i++) {
        const int r = row0 + wm * 64 + i * 16 + g;
#pragma unroll
        for (int j = 0; j < 4; j++) {
            const int c = col0 + wn * 32 + j * 8 + 2 * t;
            float v[4];
            v[0] = alpha * acc[i][j][0];
            v[1] = alpha * acc[i][j][1];
            v[2] = alpha * acc[i][j][2];
            v[3] = alpha * acc[i][j][3];
            if (bias) {
                float bx = bias[c], by = bias[c + 1];
                v[0] += bx; v[1] += by; v[2] += bx; v[3] += by;
            }
            if (Cf) {
                *(float2*)(Cf + offC + (size_t)r * ldc + c)       = make_float2(v[0], v[1]);
                *(float2*)(Cf + offC + (size_t)(r + 8) * ldc + c) = make_float2(v[2], v[3]);
            }
            if (Ch) {
                __half h0, l0, h1, l1, h2, l2, h3, l3;
                split1(v[0], h0, l0); split1(v[1], h1, l1);
                split1(v[2], h2, l2); split1(v[3], h3, l3);
                *(__half2*)(Ch + offC + (size_t)r * ldc + c)       = __halves2half2(h0, h1);
                *(__half2*)(Cl + offC + (size_t)r * ldc + c)       = __halves2half2(l0, l1);
                *(__half2*)(Ch + offC + (size_t)(r + 8) * ldc + c) = __halves2half2(h2, h3);
                *(__half2*)(Cl + offC + (size_t)(r + 8) * ldc + c) = __halves2half2(l2, l3);
            }
        }
    }
}

// ---------------------------------------------------------------------------
// Row softmax over 2048-wide rows (vectorized); writes fp16 probs (hi only).
__global__ void __launch_bounds__(256)
softmax_fp16(const float4* __restrict__ S4, __half2* __restrict__ Sh2)
{
    const size_t b4 = (size_t)blockIdx.x * 512;
    const int tid = threadIdx.x;

    float4 va = S4[b4 + tid];
    float4 vb = S4[b4 + tid + 256];

    float m = fmaxf(fmaxf(fmaxf(va.x, va.y), fmaxf(va.z, va.w)),
                    fmaxf(fmaxf(vb.x, vb.y), fmaxf(vb.z, vb.w)));

    __shared__ float red[8];
#pragma unroll
    for (int o = 16; o; o >>= 1) m = fmaxf(m, __shfl_xor_sync(0xffffffffu, m, o));
    if ((tid & 31) == 0) red[tid >> 5] = m;
    __syncthreads();
    m = red[0];
#pragma unroll
    for (int i = 1; i < 8; i++) m = fmaxf(m, red[i]);
    __syncthreads();

    va.x = __expf(va.x - m); va.y = __expf(va.y - m);
    va.z = __expf(va.z - m); va.w = __expf(va.w - m);
    vb.x = __expf(vb.x - m); vb.y = __expf(vb.y - m);
    vb.z = __expf(vb.z - m); vb.w = __expf(vb.w - m);
    float s = va.x + va.y + va.z + va.w + vb.x + vb.y + vb.z + vb.w;

#pragma unroll
    for (int o = 16; o; o >>= 1) s += __shfl_xor_sync(0xffffffffu, s, o);
    if ((tid & 31) == 0) red[tid >> 5] = s;
    __syncthreads();
    s = 0.0f;
#pragma unroll
    for (int i = 0; i < 8; i++) s += red[i];

    const float inv = 1.0f / s;
    const size_t h2base = (size_t)blockIdx.x * 1024;

    Sh2[h2base + 2 * tid] =
        __halves2half2(__float2half_rn(va.x * inv), __float2half_rn(va.y * inv));
    Sh2[h2base + 2 * tid + 1] =
        __halves2half2(__float2half_rn(va.z * inv), __float2half_rn(va.w * inv));
    Sh2[h2base + 2 * (tid + 256)] =
        __halves2half2(__float2half_rn(vb.x * inv), __float2half_rn(vb.y * inv));
    Sh2[h2base + 2 * (tid + 256) + 1] =
        __halves2half2(__float2half_rn(vb.z * inv), __float2half_rn(vb.w * inv));
}

// ---------------------------------------------------------------------------
extern "C" void kernel_launch(void* const* d_in, const int* in_sizes, int n_in,
                              void* d_out, int out_size)
{
    (void)in_sizes; (void)n_in; (void)out_size;
    const float* x     = (const float*)d_in[0];   // [4,2048,1024]
    const float* w_qkv = (const float*)d_in[1];   // [3072,1024]
    const float* w_out = (const float*)d_in[2];   // [1024,1024]
    const float* b_out = (const float*)d_in[3];   // [1024]
    float* out = (float*)d_out;                   // [4,2048,1024]

    float *S, *bufA, *bufB;
    __half *xh, *xl, *bAh, *bAl, *bBh, *bBl, *Wch, *Wcl, *yUh, *yUl, *Sh, *Ut;
    cudaGetSymbolAddress((void**)&S,    g_S);
    cudaGetSymbolAddress((void**)&xh,   g_xh);   cudaGetSymbolAddress((void**)&xl,   g_xl);
    cudaGetSymbolAddress((void**)&bufA, g_bufA); cudaGetSymbolAddress((void**)&bufB, g_bufB);
    cudaGetSymbolAddress((void**)&bAh,  g_bAh);  cudaGetSymbolAddress((void**)&bAl,  g_bAl);
    cudaGetSymbolAddress((void**)&bBh,  g_bBh);  cudaGetSymbolAddress((void**)&bBl,  g_bBl);
    cudaGetSymbolAddress((void**)&Wch,  g_Wch);  cudaGetSymbolAddress((void**)&Wcl,  g_Wcl);
    cudaGetSymbolAddress((void**)&yUh,  g_yUh);  cudaGetSymbolAddress((void**)&yUl,  g_yUl);
    cudaGetSymbolAddress((void**)&Sh,   g_Sh);
    cudaGetSymbolAddress((void**)&Ut,   g_Ut);

    const int SM3 = 3 * 4 * TILE_B;   // 98304
    const int SM1 = 3 * 2 * TILE_B;   // 49152
    cudaFuncSetAttribute(gemm_nt_split<3>,
                         cudaFuncAttributeMaxDynamicSharedMemorySize, SM3);
    cudaFuncSetAttribute(gemm_nt_split<1>,
                         cudaFuncAttributeMaxDynamicSharedMemorySize, SM1);

    // 0) split x; build packed weight operands
    {
        int n4 = 8192 * 1024 / 4;
        split_kernel<<<(n4 + 255) / 256, 256>>>((const float4*)x,
            (__half2*)xh, (__half2*)xl, n4);
    }
    // bufA = [Wk^T ; Wo],  bufB = [Wq^T ; Wv^T]
    transpose32f<<<dim3(32, 32), dim3(32, 8)>>>(w_qkv + 1024ll * 1024, bufA);
    transpose32f<<<dim3(32, 32), dim3(32, 8)>>>(w_qkv,                 bufB);
    transpose32f<<<dim3(32, 32), dim3(32, 8)>>>(w_qkv + 2048ll * 1024, bufB + 1024ll * 1024);
    cudaMemcpyAsync(bufA + 1024ll * 1024, w_out, 1024ll * 1024 * 4,
                    cudaMemcpyDeviceToDevice);
    {
        int n4 = 2048 * 1024 / 4;
        split_kernel<<<(n4 + 255) / 256, 256>>>((const float4*)bufA,
            (__half2*)bAh, (__half2*)bAl, n4);
        split_kernel<<<(n4 + 255) / 256, 256>>>((const float4*)bufB,
            (__half2*)bBh, (__half2*)bBl, n4);
    }

    // 1) weight products (batched z=2): Wc[0]=W~^T, Wc[1]=G~^T
    gemm_nt_split<3><<<dim3(8, 8, 2), 256, SM3>>>(
        bAh, bAl, bBh, bBl, nullptr, Wch, Wcl, nullptr,
        1024, 1024, 1024, 1024, 1.0f,
        1024ll * 1024, 1024ll * 1024, 1024ll * 1024);

    // 2) [y|U] = x @ Wc^T : M=8192, N=2048, K=1024 -> split yU
    gemm_nt_split<3><<<dim3(16, 64, 1), 256, SM3>>>(
        xh, xl, Wch, Wcl, nullptr, yUh, yUl, nullptr,
        1024, 1024, 2048, 1024, 1.0f, 0, 0, 0);

    // 3) S[b] = y[b] @ x[b]^T * 0.125 : fp32 out
    gemm_nt_split<3><<<dim3(16, 16, 4), 256, SM3>>>(
        yUh, yUl, xh, xl, S, nullptr, nullptr, nullptr,
        2048, 1024, 2048, 1024, 0.125f,
        2048ll * 2048, 2048ll * 1024, 2048ll * 2048);

    // 4) softmax -> fp16 probs (hi only)
    softmax_fp16<<<4 * 2048, 256>>>((const float4*)S, (__half2*)Sh);

    // 5) Ut[b] = U[b]^T (U = right half of yU, hi part)
    transpose_u<<<dim3(64, 32, 4), dim3(32, 8)>>>(yUh, Ut);

    // 6) out = Ph @ U + b_out : M=2048, N=1024, K=2048 (1-term)
    gemm_nt_split<1><<<dim3(8, 16, 4), 256, SM1>>>(
        Sh, nullptr, Ut, nullptr, out, nullptr, nullptr, b_out,
        2048, 2048, 1024, 2048, 1.0f,
        2048ll * 2048, 1024ll * 2048, 2048ll * 1024);
}